// round 5
// baseline (speedup 1.0000x reference)
#include <cuda_runtime.h>
#include <cuda_bf16.h>

// CSR multi-head SpMM: out[n,h,d] = sum_{e in row n} ew[e,h] * nf[col[e],h,d]
// N=50000, E=800000, H=8, D=8 -> 64 floats per row.
//
// R4: HALF-WARP per row. Lanes 0-15 process row 2w, lanes 16-31 row 2w+1.
// Sub-lane s owns floats [4s, 4s+3] (one float4), head h = s>>1.
// Each loop iteration handles one edge of EACH row -> two independent
// dependent-load chains share one instruction stream: per-warp work per
// exposed L2 round-trip doubles at zero extra register cost vs R1.
// Feature gather per row = 16 lanes x 16B = 256B coalesced (L2-resident).

#define H 8
#define D 8
#define ROW_ELEMS (H * D)

__global__ __launch_bounds__(256) void spmm_csr_kernel(
    const int* __restrict__ row_ptr,
    const int* __restrict__ col_idx,
    const float* __restrict__ edge_weight,   // [E, 8]
    const float* __restrict__ node_feat,     // [N, 64]
    float* __restrict__ out,                 // [N, 64]
    int n_nodes)
{
    int gwarp = (blockIdx.x * blockDim.x + threadIdx.x) >> 5;
    int lane  = threadIdx.x & 31;
    int half  = lane >> 4;                 // which row of the pair
    int s     = lane & 15;                 // sub-lane within the half-warp

    int row = gwarp * 2 + half;
    if (gwarp * 2 >= n_nodes) return;      // whole warp idle

    bool valid = (row < n_nodes);
    int start = 0, end = 0;
    if (valid) {
        start = __ldg(&row_ptr[row]);
        end   = __ldg(&row_ptr[row + 1]);
    }

    int h = s >> 1;                        // head index for this float4
    float ax = 0.f, ay = 0.f, az = 0.f, aw = 0.f;

    #pragma unroll 4
    for (int e = start; e < end; ++e) {
        int c   = __ldg(&col_idx[e]);
        float w = __ldg(&edge_weight[(size_t)e * H + h]);
        float4 f = *reinterpret_cast<const float4*>(
            node_feat + (size_t)c * ROW_ELEMS + s * 4);
        ax = fmaf(w, f.x, ax);
        ay = fmaf(w, f.y, ay);
        az = fmaf(w, f.z, az);
        aw = fmaf(w, f.w, aw);
    }

    if (valid) {
        float4 r; r.x = ax; r.y = ay; r.z = az; r.w = aw;
        *reinterpret_cast<float4*>(out + (size_t)row * ROW_ELEMS + s * 4) = r;
    }
}

extern "C" void kernel_launch(void* const* d_in, const int* in_sizes, int n_in,
                              void* d_out, int out_size)
{
    const int*   row_ptr     = (const int*)d_in[0];
    const int*   col_idx     = (const int*)d_in[1];
    const float* edge_weight = (const float*)d_in[2];
    const float* node_feat   = (const float*)d_in[3];
    float*       out         = (float*)d_out;

    int n_nodes = in_sizes[0] - 1;          // row_ptr has N+1 entries

    const int threads = 256;                 // 8 warps/block, 2 rows/warp
    int warps  = (n_nodes + 1) / 2;
    int blocks = (warps * 32 + threads - 1) / threads;
    spmm_csr_kernel<<<blocks, threads>>>(row_ptr, col_idx, edge_weight,
                                         node_feat, out, n_nodes);
}